// round 17
// baseline (speedup 1.0000x reference)
#include <cuda_runtime.h>
#include <cuda_fp16.h>
#include <cstdint>

#define N_ROWS   16384
#define N_CODES  8192
#define DIM      64
#define BM       128
#define BN       64
#define NQ       4                    // code-dimension split
#define NCHUNKQ  (N_CODES / BN / NQ)  // 32 chunks per quarter
#define THREADS  256
#define ROWB     272                  // 17*16B; 17 mod 8 = 1 -> conflict-free LDSM
#define CGSTRIDE (16 * ROWB)
#define BBUF     (BN * ROWB)          // 17408 B per B stage
#define NTILE    (N_ROWS / BM)        // 128 row tiles
#define NARG     (NTILE * NQ)         // 512 argmin CTAs
#define NZERO    128                  // zerofill CTAs (1-in-5 interleaved)
#define DISC_F4  ((size_t)N_ROWS * N_CODES / 4)
#define SMEMSZ   (BM * ROWB + 2 * BBUF)          // 69632 (x2 = 139264 < 228KB)

// device scratch: [ch(128B) | cl(128B)] per code
__device__ __align__(16) __half g_cbe[(size_t)N_CODES * 128];
__device__ __align__(16) float  g_cnorm[N_CODES];
__device__ unsigned long long g_red[N_ROWS];

// ---------------- helpers ----------------
__device__ __forceinline__ uint32_t h2_as_u32(__half2 h) {
    uint32_t u;
    __builtin_memcpy(&u, &h, 4);
    return u;
}
__device__ __forceinline__ uint32_t pack_h2(__half a, __half b) {
    return h2_as_u32(__halves2half2(a, b));
}
__device__ __forceinline__ uint32_t smem_u32(const void* p) {
    uint32_t a;
    asm("{ .reg .u64 t; cvta.to.shared.u64 t, %1; cvt.u32.u64 %0, t; }" : "=r"(a) : "l"(p));
    return a;
}
__device__ __forceinline__ unsigned ord_f32(float f) {
    unsigned u = __float_as_uint(f);
    return (u & 0x80000000u) ? ~u : (u | 0x80000000u);
}
#define CPA16(d,s)   asm volatile("cp.async.cg.shared.global [%0], [%1], 16;" :: "r"(d), "l"(s) : "memory")
#define CPA_COMMIT() asm volatile("cp.async.commit_group;" ::: "memory")
#define CPA_WAIT0()  asm volatile("cp.async.wait_group 0;" ::: "memory")

#define LDM_X4(r0,r1,r2,r3,a) \
    asm volatile("ldmatrix.sync.aligned.m8n8.x4.shared.b16 {%0,%1,%2,%3}, [%4];" \
                 : "=r"(r0), "=r"(r1), "=r"(r2), "=r"(r3) : "r"(a))

__device__ __forceinline__ void mma16816(float* d, const uint32_t* a,
                                         uint32_t b0, uint32_t b1) {
    asm volatile("mma.sync.aligned.m16n8k16.row.col.f32.f16.f16.f32 "
                 "{%0,%1,%2,%3}, {%4,%5,%6,%7}, {%8,%9}, {%0,%1,%2,%3};"
                 : "+f"(d[0]), "+f"(d[1]), "+f"(d[2]), "+f"(d[3])
                 : "r"(a[0]), "r"(a[1]), "r"(a[2]), "r"(a[3]), "r"(b0), "r"(b1));
}

// ---------------------------------------------------------------------------
// Prep: codebook -> fp16 [ch|cl] + squared norms; also init g_red.
// ---------------------------------------------------------------------------
__global__ void prep_kernel(const float* __restrict__ cb) {
    int g = blockIdx.x * blockDim.x + threadIdx.x;
    if (g < N_ROWS) g_red[g] = ~0ULL;
    int code = g >> 5, lane = g & 31;
    float2 v = reinterpret_cast<const float2*>(cb + (size_t)code * DIM)[lane];
    __half hx = __float2half_rn(v.x), hy = __float2half_rn(v.y);
    float lx = v.x - __half2float(hx), ly = v.y - __half2float(hy);
    __half2* dst = reinterpret_cast<__half2*>(g_cbe + (size_t)code * 128);
    dst[lane]      = __halves2half2(hx, hy);
    dst[32 + lane] = __halves2half2(__float2half_rn(lx), __float2half_rn(ly));
    float s = v.x * v.x + v.y * v.y;
#pragma unroll
    for (int o = 16; o; o >>= 1) s += __shfl_xor_sync(~0u, s, o);
    if (lane == 0) g_cnorm[code] = s;
}

// ---------------------------------------------------------------------------
// Fused, interleaved roles: bid%5==4 -> zerofill; else argmin over one
// (row-tile, code-quarter). Cross-CTA merge via packed u64 atomicMin.
// ---------------------------------------------------------------------------
__global__ void __launch_bounds__(THREADS, 2)
argmin_fused(const float* __restrict__ x, const float* __restrict__ cb,
             float* __restrict__ out_disc) {
    const int tid = threadIdx.x;
    const int m = blockIdx.x % 5, dgrp = blockIdx.x / 5;

    if (m == 4) {
        // ---- zerofill CTA (zid = dgrp in [0,128)) ----
        size_t i = (size_t)dgrp * THREADS + tid;
        const size_t stride = (size_t)NZERO * THREADS;
        float4 z = make_float4(0.f, 0.f, 0.f, 0.f);
        float4* o = reinterpret_cast<float4*>(out_disc);
#pragma unroll 4
        for (; i < DISC_F4; i += stride) __stcs(o + i, z);
        return;
    }

    const int aidx = dgrp * 4 + m;            // [0, 512)
    const int row0 = (aidx >> 2) * BM;
    const int q    = aidx & 3;                // code quarter
    const int gc0  = q * NCHUNKQ;             // first global chunk

    extern __shared__ char smem[];
    const uint32_t As = smem_u32(smem);                 // [128][272] : [xh|xl]
    const uint32_t Bs = As + BM * ROWB;                 // B ring [2][17408]

    const int wid = tid >> 5, lane = tid & 31;

    // ---- Build A staging: row = [xh(128B) | xl(128B)] ----
    for (int t = tid; t < BM * (DIM / 4); t += THREADS) {
        int row = t >> 4, qq = t & 15;
        float4 v = reinterpret_cast<const float4*>(x)[(size_t)(row0 + row) * 16 + qq];
        __half h0 = __float2half_rn(v.x), h1 = __float2half_rn(v.y);
        __half h2 = __float2half_rn(v.z), h3 = __float2half_rn(v.w);
        uint32_t hp0 = pack_h2(h0, h1);
        uint32_t hp1 = pack_h2(h2, h3);
        uint32_t lp0 = pack_h2(__float2half_rn(v.x - __half2float(h0)),
                               __float2half_rn(v.y - __half2float(h1)));
        uint32_t lp1 = pack_h2(__float2half_rn(v.z - __half2float(h2)),
                               __float2half_rn(v.w - __half2float(h3)));
        uint32_t base = As + row * ROWB + qq * 8;
        asm volatile("st.shared.v2.b32 [%0], {%1,%2};" :: "r"(base), "r"(hp0), "r"(hp1));
        asm volatile("st.shared.v2.b32 [%0], {%1,%2};" :: "r"(base + 128), "r"(lp0), "r"(lp1));
    }
    __syncthreads();

    // ---- Persistent A fragments: kgroups 0-3 = xh, 4-7 = xl ----
    uint32_t afr[8][4];
    {
        int t = lane >> 3;
        int arow = wid * 16 + ((t & 1) << 3) + (lane & 7);
        uint32_t abase = As + arow * ROWB + ((t >> 1) << 4);
#pragma unroll
        for (int kg = 0; kg < 8; kg++)
            LDM_X4(afr[kg][0], afr[kg][1], afr[kg][2], afr[kg][3], abase + kg * 32);
    }
    __syncthreads();

    const uint32_t bl0 = Bs + (((lane >> 4) << 3) + (lane & 7)) * ROWB
                       + ((lane >> 3) & 1) * 16;

    // ---- prefetch first chunk of this quarter ----
    {
        const char* src = (const char*)g_cbe + (size_t)gc0 * BN * 256;
#pragma unroll
        for (int j = 0; j < 4; j++) {
            int i = tid + j * THREADS;
            int code = i >> 4, off = (i & 15) * 16;
            CPA16(Bs + code * ROWB + off, src + i * 16);
        }
        CPA_COMMIT();
    }

    float best0 = 3.4e38f, best1 = 3.4e38f;
    int idx0 = 0, idx1 = 0;

    for (int c = 0; c < NCHUNKQ; c++) {
        CPA_WAIT0();
        __syncthreads();
        if (c + 1 < NCHUNKQ) {
            const char* src = (const char*)g_cbe + (size_t)(gc0 + c + 1) * BN * 256;
            uint32_t dbuf = Bs + ((c + 1) & 1) * BBUF;
#pragma unroll
            for (int j = 0; j < 4; j++) {
                int i = tid + j * THREADS;
                int code = i >> 4, off = (i & 15) * 16;
                CPA16(dbuf + code * ROWB + off, src + i * 16);
            }
            CPA_COMMIT();
        }

        const uint32_t bb = bl0 + (c & 1) * BBUF;
        float acc[8][4];
#pragma unroll
        for (int f = 0; f < 8; f++)
#pragma unroll
            for (int j = 0; j < 4; j++) acc[f][j] = 0.f;

        // passes 1+2: per kgroup, load ch frags (4 LDM), sweep acc0..7 twice
#pragma unroll
        for (int t = 0; t < 4; t++) {
            uint32_t b[4][4];
#pragma unroll
            for (int cg = 0; cg < 4; cg++)
                LDM_X4(b[cg][0], b[cg][1], b[cg][2], b[cg][3],
                       bb + cg * CGSTRIDE + t * 32);
#pragma unroll
            for (int cg = 0; cg < 4; cg++) {
                mma16816(acc[2 * cg],     afr[t], b[cg][0], b[cg][1]);
                mma16816(acc[2 * cg + 1], afr[t], b[cg][2], b[cg][3]);
            }
#pragma unroll
            for (int cg = 0; cg < 4; cg++) {
                mma16816(acc[2 * cg],     afr[4 + t], b[cg][0], b[cg][1]);
                mma16816(acc[2 * cg + 1], afr[4 + t], b[cg][2], b[cg][3]);
            }
        }
        // pass 3: xh . cl
#pragma unroll
        for (int t = 0; t < 4; t++) {
            uint32_t b[4][4];
#pragma unroll
            for (int cg = 0; cg < 4; cg++)
                LDM_X4(b[cg][0], b[cg][1], b[cg][2], b[cg][3],
                       bb + 128 + cg * CGSTRIDE + t * 32);
#pragma unroll
            for (int cg = 0; cg < 4; cg++) {
                mma16816(acc[2 * cg],     afr[t], b[cg][0], b[cg][1]);
                mma16816(acc[2 * cg + 1], afr[t], b[cg][2], b[cg][3]);
            }
        }

        int base = (gc0 + c) * BN + ((lane & 3) << 1);
#pragma unroll
        for (int f = 0; f < 8; f++) {
            int col = base + f * 8;
            float cn0 = __ldg(&g_cnorm[col]);
            float cn1 = __ldg(&g_cnorm[col + 1]);
            float d0 = fmaf(-2.f, acc[f][0], cn0);
            float d1 = fmaf(-2.f, acc[f][1], cn1);
            float d2 = fmaf(-2.f, acc[f][2], cn0);
            float d3 = fmaf(-2.f, acc[f][3], cn1);
            if (d0 < best0) { best0 = d0; idx0 = col; }
            if (d1 < best0) { best0 = d1; idx0 = col + 1; }
            if (d2 < best1) { best1 = d2; idx1 = col; }
            if (d3 < best1) { best1 = d3; idx1 = col + 1; }
        }
    }

    // reduce across the 4 lanes sharing each row; tie -> lowest index
#pragma unroll
    for (int off = 1; off <= 2; off <<= 1) {
        float ob = __shfl_xor_sync(~0u, best0, off);
        int   oi = __shfl_xor_sync(~0u, idx0, off);
        if (ob < best0 || (ob == best0 && oi < idx0)) { best0 = ob; idx0 = oi; }
        ob = __shfl_xor_sync(~0u, best1, off);
        oi = __shfl_xor_sync(~0u, idx1, off);
        if (ob < best1 || (ob == best1 && oi < idx1)) { best1 = ob; idx1 = oi; }
    }
    if ((lane & 3) == 0) {
        int r = wid * 16 + (lane >> 2);
        unsigned long long k0 = ((unsigned long long)ord_f32(best0) << 32) | (unsigned)idx0;
        unsigned long long k1 = ((unsigned long long)ord_f32(best1) << 32) | (unsigned)idx1;
        atomicMin(&g_red[row0 + r], k0);
        atomicMin(&g_red[row0 + r + 8], k1);
    }
}

// ---------------------------------------------------------------------------
// Finalize: gather quantized rows + scatter the 1.0s from the global winners.
// ---------------------------------------------------------------------------
__global__ void finalize_kernel(const float* __restrict__ cb,
                                float* __restrict__ out_disc,
                                float* __restrict__ outq) {
    unsigned i = blockIdx.x * 256u + threadIdx.x;
    unsigned n = i >> 4;
    unsigned c4 = i & 15u;
    int k = (int)(g_red[n] & 0xffffffffu);
    reinterpret_cast<float4*>(outq)[i] =
        reinterpret_cast<const float4*>(cb + (size_t)k * DIM)[c4];
    if (c4 == 0) out_disc[(size_t)n * N_CODES + k] = 1.0f;
}

// ---------------------------------------------------------------------------
extern "C" void kernel_launch(void* const* d_in, const int* in_sizes, int n_in,
                              void* d_out, int out_size) {
    const float* x  = (const float*)d_in[0];
    const float* cb = (const float*)d_in[1];
    float* out      = (float*)d_out;
    float* out_disc = out;
    float* out_q    = out + (size_t)N_ROWS * N_CODES;

    cudaFuncSetAttribute(argmin_fused, cudaFuncAttributeMaxDynamicSharedMemorySize, SMEMSZ);

    prep_kernel<<<(N_CODES * 32) / 256, 256>>>(cb);
    argmin_fused<<<NARG + NZERO, THREADS, SMEMSZ>>>(x, cb, out_disc);
    finalize_kernel<<<(N_ROWS * (DIM / 4)) / 256, 256>>>(cb, out_disc, out_q);
}